// round 16
// baseline (speedup 1.0000x reference)
#include <cuda_runtime.h>
#include <cuda_fp16.h>
#include <stdint.h>

#define S_LEN 2048
#define DM 512
#define NH 8
#define WIN 64
#define SCALE 0.125f
#define WSZ (512*512)
#define XSZ (2048*512)

// ---------------- scratch (no allocation allowed) ----------------
__device__ __align__(16) __half g_x_hi[XSZ];                     // x: hi only
__device__ __align__(16) __half g_w_hi[4 * WSZ];                 // weights: hi only
__device__ __align__(16) __half g_q_hi[XSZ];                     // q: hi only
__device__ __align__(16) __half g_k_hi[XSZ];                     // K: hi only
__device__ __align__(16) __half g_vt_hi[XSZ];                    // V^T: hi only [512][2048]
__device__ __align__(16) __half g_a_hi[XSZ];                     // attn out: hi only

// ---------------- PTX helpers (baseline sm_80+, compile for compute_103) -----
__device__ __forceinline__ uint32_t smem_u32(const void* p) {
    uint32_t a;
    asm("{ .reg .u64 t; cvta.to.shared.u64 t, %1; cvt.u32.u64 %0, t; }"
        : "=r"(a) : "l"(p));
    return a;
}
__device__ __forceinline__ void cp16(uint32_t s, const void* g) {
    asm volatile("cp.async.cg.shared.global [%0], [%1], 16;"
                 :: "r"(s), "l"(g) : "memory");
}
__device__ __forceinline__ void cp_commit() {
    asm volatile("cp.async.commit_group;" ::: "memory");
}
template<int N> __device__ __forceinline__ void cp_wait() {
    asm volatile("cp.async.wait_group %0;" :: "n"(N) : "memory");
}
__device__ __forceinline__ void ldsm_x4(uint32_t& r0, uint32_t& r1,
                                        uint32_t& r2, uint32_t& r3, uint32_t a) {
    asm volatile("ldmatrix.sync.aligned.m8n8.x4.shared.b16 {%0,%1,%2,%3}, [%4];"
                 : "=r"(r0), "=r"(r1), "=r"(r2), "=r"(r3) : "r"(a));
}
__device__ __forceinline__ void mma16816(float c[4], const uint32_t a[4],
                                         const uint32_t b[2]) {
    asm volatile(
        "mma.sync.aligned.m16n8k16.row.col.f32.f16.f16.f32 "
        "{%0,%1,%2,%3}, {%4,%5,%6,%7}, {%8,%9}, {%0,%1,%2,%3};"
        : "+f"(c[0]), "+f"(c[1]), "+f"(c[2]), "+f"(c[3])
        : "r"(a[0]), "r"(a[1]), "r"(a[2]), "r"(a[3]), "r"(b[0]), "r"(b[1]));
}

// ---------------- conversion: fp32 -> fp16 (hi only) --------------------------
__global__ __launch_bounds__(256)
void convert_split(const float* __restrict__ x,
                   const float* __restrict__ wq, const float* __restrict__ wk,
                   const float* __restrict__ wv, const float* __restrict__ wo)
{
    const int tn = blockIdx.y;
    const float* src = (tn == 0) ? x : (tn == 1) ? wq : (tn == 2) ? wk
                       : (tn == 3) ? wv : wo;
    const int n = (tn == 0) ? XSZ : WSZ;
    __half* hi = (tn == 0) ? g_x_hi : g_w_hi + (tn - 1) * WSZ;
    int i4 = (blockIdx.x * 256 + threadIdx.x) * 4;
    if (i4 >= n) return;
    float4 v = *reinterpret_cast<const float4*>(&src[i4]);
    reinterpret_cast<__half2*>(hi + i4)[0] =
        __halves2half2(__float2half_rn(v.x), __float2half_rn(v.y));
    reinterpret_cast<__half2*>(hi + i4)[1] =
        __halves2half2(__float2half_rn(v.z), __float2half_rn(v.w));
}

// ---------------- QKV: 1-term fp16 GEMM, 128x64 tile, 3-stage ring -----------
#define QOBH (128 * 144)
#define QGBUF ((128 + 64) * 144)
#define QKV_SMEM (QGBUF * 3)     // 82944

__global__ __launch_bounds__(128, 2)
void gemm_qkv_mma(const float* __restrict__ bq, const float* __restrict__ bk,
                  const float* __restrict__ bv)
{
    const int which = blockIdx.x >> 3;
    const int colBase = (blockIdx.x & 7) * 64;
    const int rowBase = blockIdx.y * 128;
    const float* bias = (which == 0) ? bq : (which == 1) ? bk : bv;
    __half* oh; int mode;
    if (which == 0)      { oh = g_q_hi;  mode = 0; }
    else if (which == 1) { oh = g_k_hi;  mode = 0; }
    else                 { oh = g_vt_hi; mode = 1; }
    const __half* A = g_x_hi;
    const __half* B = g_w_hi + which * WSZ;

    extern __shared__ __align__(16) char dynsm[];
    const uint32_t sb = smem_u32(dynsm);
    const int tid = threadIdx.x, lane = tid & 31, wid = tid >> 5;
    const int wm = wid >> 1, wn = wid & 1;           // 2x2 warps, 64x32 tile
    const int a_row = (lane & 7) + ((lane >> 3) & 1) * 8, a_k = (lane >> 4) * 8;
    const int b_row = (lane & 7) + (lane >> 4) * 8,       b_k = ((lane >> 3) & 1) * 8;

    float acc[4][4][4] = {};

    auto stage = [&](int buf, int c) {
#pragma unroll
        for (int i = 0; i < 12; i++) {               // (1024+512) cp16 / 128 thr
            int idx = tid + i * 128;
            const __half* src; int off, rbase, rem;
            if (idx < 1024) { src = A; off = 0;    rbase = rowBase; rem = idx; }
            else            { src = B; off = QOBH; rbase = colBase; rem = idx - 1024; }
            int row = rem >> 3, cc = rem & 7;
            cp16(sb + (uint32_t)(buf * QGBUF + off + row * 144 + cc * 16),
                 src + ((size_t)(rbase + row) * DM + c * 64 + cc * 8));
        }
        cp_commit();
    };

    stage(0, 0); stage(1, 1);
    for (int c = 0; c < 8; c++) {
        if (c < 7) cp_wait<1>();
        else       cp_wait<0>();
        __syncthreads();
        if (c < 6) stage((c + 2) % 3, c + 2);
        const uint32_t bb = sb + (uint32_t)((c % 3) * QGBUF);
#pragma unroll
        for (int k16 = 0; k16 < 4; k16++) {
            uint32_t ah[4][4], bh[4][2];
#pragma unroll
            for (int mi = 0; mi < 4; mi++) {
                uint32_t o = (uint32_t)((wm * 64 + mi * 16 + a_row) * 144 +
                                        (k16 * 16 + a_k) * 2);
                ldsm_x4(ah[mi][0], ah[mi][1], ah[mi][2], ah[mi][3], bb + o);
            }
#pragma unroll
            for (int bn = 0; bn < 2; bn++) {
                uint32_t o = (uint32_t)((wn * 32 + bn * 16 + b_row) * 144 +
                                        (k16 * 16 + b_k) * 2);
                uint32_t r0, r1, r2, r3;
                ldsm_x4(r0, r1, r2, r3, bb + QOBH + o);
                bh[bn * 2][0] = r0; bh[bn * 2][1] = r1;
                bh[bn * 2 + 1][0] = r2; bh[bn * 2 + 1][1] = r3;
            }
#pragma unroll
            for (int mi = 0; mi < 4; mi++)
#pragma unroll
                for (int ni = 0; ni < 4; ni++)
                    mma16816(acc[mi][ni], ah[mi], bh[ni]);
        }
    }

#pragma unroll
    for (int mi = 0; mi < 4; mi++) {
        int row = rowBase + wm * 64 + mi * 16 + (lane >> 2);
#pragma unroll
        for (int ni = 0; ni < 4; ni++) {
            int col = colBase + wn * 32 + ni * 8 + (lane & 3) * 2;
            float b0 = bias[col], b1 = bias[col + 1];
            float v00 = acc[mi][ni][0] + b0, v01 = acc[mi][ni][1] + b1;
            float v10 = acc[mi][ni][2] + b0, v11 = acc[mi][ni][3] + b1;
            if (mode == 0) {
                *reinterpret_cast<__half2*>(&oh[(size_t)row * DM + col]) =
                    __halves2half2(__float2half_rn(v00), __float2half_rn(v01));
                *reinterpret_cast<__half2*>(&oh[(size_t)(row + 8) * DM + col]) =
                    __halves2half2(__float2half_rn(v10), __float2half_rn(v11));
            } else {
                oh[(size_t)col * S_LEN + row] = __float2half_rn(v00);
                oh[(size_t)(col + 1) * S_LEN + row] = __float2half_rn(v01);
                oh[(size_t)col * S_LEN + row + 8] = __float2half_rn(v10);
                oh[(size_t)(col + 1) * S_LEN + row + 8] = __float2half_rn(v11);
            }
        }
    }
}

// ---------------- O GEMM: whole-K single-phase, zero loop barriers -----------
// A-tile 32x512 + B-tile 64x512 fp16, rows 1040B (conflict-free LDSM).
#define O_ROWB 1040
#define O_B_OFF (32 * O_ROWB)
#define O_SMEM ((32 + 64) * O_ROWB)     // 99840

__global__ __launch_bounds__(128, 2)
void gemm_o_mma(const float* __restrict__ bo, float* __restrict__ out)
{
    const int rowBase = blockIdx.y * 32;
    const int colBase = blockIdx.x * 64;
    const __half* A = g_a_hi;
    const __half* B = g_w_hi + 3 * WSZ;

    extern __shared__ __align__(16) char dynsm[];
    const uint32_t sb = smem_u32(dynsm);
    const int tid = threadIdx.x, lane = tid & 31, wid = tid >> 5;
    const int wm = wid >> 1, wn = wid & 1;           // 2x2 warps, 16x32 tile
    const int a_row = (lane & 7) + ((lane >> 3) & 1) * 8, a_k = (lane >> 4) * 8;
    const int b_row = (lane & 7) + (lane >> 4) * 8,       b_k = ((lane >> 3) & 1) * 8;

    // single burst: 96 rows x 64 cp16 = 6144 cp16 / 128 thr = 48 each
#pragma unroll
    for (int i = 0; i < 48; i++) {
        int idx = tid + i * 128;
        int row = idx >> 6, cc = idx & 63;
        const __half* src = (row < 32)
            ? A + ((size_t)(rowBase + row) * DM + cc * 8)
            : B + ((size_t)(colBase + row - 32) * DM + cc * 8);
        cp16(sb + (uint32_t)(row * O_ROWB + cc * 16), src);
    }
    cp_commit();
    cp_wait<0>();
    __syncthreads();

    float acc[4][4] = {};
#pragma unroll
    for (int c = 0; c < 8; c++) {
#pragma unroll
        for (int k16 = 0; k16 < 4; k16++) {
            uint32_t ah[4], bh[4][2];
            uint32_t oA = (uint32_t)((wm * 16 + a_row) * O_ROWB +
                                     (c * 64 + k16 * 16 + a_k) * 2);
            ldsm_x4(ah[0], ah[1], ah[2], ah[3], sb + oA);
#pragma unroll
            for (int bn = 0; bn < 2; bn++) {
                uint32_t oB = (uint32_t)(O_B_OFF +
                                         (wn * 32 + bn * 16 + b_row) * O_ROWB +
                                         (c * 64 + k16 * 16 + b_k) * 2);
                uint32_t r0, r1, r2, r3;
                ldsm_x4(r0, r1, r2, r3, sb + oB);
                bh[bn * 2][0] = r0; bh[bn * 2][1] = r1;
                bh[bn * 2 + 1][0] = r2; bh[bn * 2 + 1][1] = r3;
            }
#pragma unroll
            for (int ni = 0; ni < 4; ni++)
                mma16816(acc[ni], ah, bh[ni]);
        }
    }

    int row = rowBase + wm * 16 + (lane >> 2);
#pragma unroll
    for (int ni = 0; ni < 4; ni++) {
        int col = colBase + wn * 32 + ni * 8 + (lane & 3) * 2;
        float b0 = bo[col], b1 = bo[col + 1];
        *reinterpret_cast<float2*>(&out[(size_t)row * DM + col]) =
            make_float2(acc[ni][0] + b0, acc[ni][1] + b1);
        *reinterpret_cast<float2*>(&out[(size_t)(row + 8) * DM + col]) =
            make_float2(acc[ni][2] + b0, acc[ni][3] + b1);
    }
}

// ---------------- tensor-core banded attention (1-term everywhere) -----------
#define AQH 0
#define AKH 9216
#define AVH 36864
#define ASF 62464
#define APH AKH              /* P (64x400B=25600) overlays K (27648) */
#define ATTN_B 113664

__global__ __launch_bounds__(256)
void attn_mma()
{
    extern __shared__ __align__(16) char dynsm[];
    const uint32_t sb = smem_u32(dynsm);
    const int tid = threadIdx.x, lane = tid & 31, wid = tid >> 5;
    const int h = blockIdx.y;
    const int base = blockIdx.x * 64;
    const int j0 = base - WIN;

#pragma unroll
    for (int i = 0; i < 2; i++) {                       // Q hi [64][64]
        int idx = tid + i * 256;
        int row = idx >> 3, cc = idx & 7;
        cp16(sb + AQH + (uint32_t)(row * 144 + cc * 16),
             g_q_hi + ((size_t)(base + row) * DM + h * 64 + cc * 8));
    }
#pragma unroll
    for (int i = 0; i < 6; i++) {                       // K hi [192][64]
        int idx = tid + i * 256;
        int row = idx >> 3, cc = idx & 7;
        int j = j0 + row;
        uint32_t off = AKH + (uint32_t)(row * 144 + cc * 16);
        if (j >= 0 && j < S_LEN)
            cp16(sb + off, g_k_hi + ((size_t)j * DM + h * 64 + cc * 8));
        else
            *reinterpret_cast<uint4*>(dynsm + off) = make_uint4(0, 0, 0, 0);
    }
#pragma unroll
    for (int i = 0; i < 6; i++) {                       // V^T hi [64][192]
        int idx = tid + i * 256;
        int row = idx / 24, cc = idx % 24;
        int j = j0 + cc * 8;
        uint32_t off = AVH + (uint32_t)(row * 400 + cc * 16);
        if (j >= 0 && j + 8 <= S_LEN)
            cp16(sb + off, g_vt_hi + ((size_t)(h * 64 + row) * S_LEN + j));
        else
            *reinterpret_cast<uint4*>(dynsm + off) = make_uint4(0, 0, 0, 0);
    }
    cp_commit();
    cp_wait<0>();
    __syncthreads();

    const int a_row = (lane & 7) + ((lane >> 3) & 1) * 8, a_k = (lane >> 4) * 8;
    const int b_row = (lane & 7) + (lane >> 4) * 8,       b_k = ((lane >> 3) & 1) * 8;
    const int wm = wid >> 1, wn = wid & 1;

    // ---- S = Qh·Kh^T ----
    {
        float sacc[12][4] = {};
#pragma unroll
        for (int k16 = 0; k16 < 4; k16++) {
            uint32_t ah[4];
            uint32_t oA = (uint32_t)((wm * 16 + a_row) * 144 + (k16 * 16 + a_k) * 2);
            ldsm_x4(ah[0], ah[1], ah[2], ah[3], sb + AQH + oA);
#pragma unroll
            for (int t = 0; t < 6; t++) {
                uint32_t oB = (uint32_t)((wn * 96 + t * 16 + b_row) * 144 +
                                         (k16 * 16 + b_k) * 2);
                uint32_t r0, r1, r2, r3, b0[2], b1[2];
                ldsm_x4(r0, r1, r2, r3, sb + AKH + oB);
                b0[0] = r0; b0[1] = r1; b1[0] = r2; b1[1] = r3;
                mma16816(sacc[t * 2], ah, b0);
                mma16816(sacc[t * 2 + 1], ah, b1);
            }
        }
        float* S = reinterpret_cast<float*>(dynsm + ASF);
        int row = wm * 16 + (lane >> 2);
#pragma unroll
        for (int t = 0; t < 12; t++) {
            int col = wn * 96 + t * 8 + (lane & 3) * 2;
            *reinterpret_cast<float2*>(&S[row * 200 + col]) =
                make_float2(sacc[t][0], sacc[t][1]);
            *reinterpret_cast<float2*>(&S[(row + 8) * 200 + col]) =
                make_float2(sacc[t][2], sacc[t][3]);
        }
    }
    __syncthreads();

    // ---- masked softmax; write normalized P (fp16) over K ----
    {
        float* S = reinterpret_cast<float*>(dynsm + ASF);
#pragma unroll
        for (int r8 = 0; r8 < 8; r8++) {
            int m = wid * 8 + r8;
            int nlo = m, nhi = m + 128;
            if (-j0 > nlo) nlo = -j0;
            if (2047 - j0 < nhi) nhi = 2047 - j0;
            float v[6], mx = -1e30f;
#pragma unroll
            for (int i = 0; i < 6; i++) {
                int n = lane + 32 * i;
                float sv = S[m * 200 + n] * SCALE;
                v[i] = (n >= nlo && n <= nhi) ? sv : -1e30f;
                mx = fmaxf(mx, v[i]);
            }
#pragma unroll
            for (int o = 16; o; o >>= 1)
                mx = fmaxf(mx, __shfl_xor_sync(0xffffffffu, mx, o));
            float e[6], sum = 0.f;
#pragma unroll
            for (int i = 0; i < 6; i++) { e[i] = __expf(v[i] - mx); sum += e[i]; }
#pragma unroll
            for (int o = 16; o; o >>= 1)
                sum += __shfl_xor_sync(0xffffffffu, sum, o);
            float inv = 1.f / sum;
#pragma unroll
            for (int i = 0; i < 6; i++) {
                int n = lane + 32 * i;
                *reinterpret_cast<__half*>(dynsm + APH + m * 400 + n * 2) =
                    __float2half_rn(e[i] * inv);
            }
        }
    }
    __syncthreads();

    // ---- O = Ph·Vh ----
    {
        float oacc[4][4] = {};
#pragma unroll
        for (int k16 = 0; k16 < 12; k16++) {
            uint32_t ph[4];
            uint32_t oA = (uint32_t)((wm * 16 + a_row) * 400 + (k16 * 16 + a_k) * 2);
            ldsm_x4(ph[0], ph[1], ph[2], ph[3], sb + APH + oA);
#pragma unroll
            for (int bn = 0; bn < 2; bn++) {
                uint32_t oB = (uint32_t)((wn * 32 + bn * 16 + b_row) * 400 +
                                         (k16 * 16 + b_k) * 2);
                uint32_t r0, r1, r2, r3, vh0[2], vh1[2];
                ldsm_x4(r0, r1, r2, r3, sb + AVH + oB);
                vh0[0] = r0; vh0[1] = r1; vh1[0] = r2; vh1[1] = r3;
                mma16816(oacc[bn * 2], ph, vh0);
                mma16816(oacc[bn * 2 + 1], ph, vh1);
            }
        }
        int row = base + wm * 16 + (lane >> 2);
#pragma unroll
        for (int t = 0; t < 4; t++) {
            int col = h * 64 + wn * 32 + t * 8 + (lane & 3) * 2;
            *reinterpret_cast<__half2*>(&g_a_hi[(size_t)row * DM + col]) =
                __halves2half2(__float2half_rn(oacc[t][0]), __float2half_rn(oacc[t][1]));
            *reinterpret_cast<__half2*>(&g_a_hi[(size_t)(row + 8) * DM + col]) =
                __halves2half2(__float2half_rn(oacc[t][2]), __float2half_rn(oacc[t][3]));
        }
    }
}

// ---------------- launch ----------------
extern "C" void kernel_launch(void* const* d_in, const int* in_sizes, int n_in,
                              void* d_out, int out_size) {
    const float* x  = (const float*)d_in[0];
    const float* Wq = (const float*)d_in[1];
    const float* bq = (const float*)d_in[2];
    const float* Wk = (const float*)d_in[3];
    const float* bk = (const float*)d_in[4];
    const float* Wv = (const float*)d_in[5];
    const float* bv = (const float*)d_in[6];
    const float* Wo = (const float*)d_in[7];
    const float* bo = (const float*)d_in[8];
    float* out = (float*)d_out;

    cudaFuncSetAttribute(gemm_qkv_mma, cudaFuncAttributeMaxDynamicSharedMemorySize, QKV_SMEM);
    cudaFuncSetAttribute(gemm_o_mma, cudaFuncAttributeMaxDynamicSharedMemorySize, O_SMEM);
    cudaFuncSetAttribute(attn_mma, cudaFuncAttributeMaxDynamicSharedMemorySize, ATTN_B);

    convert_split<<<dim3(XSZ / 1024, 5), 256>>>(x, Wq, Wk, Wv, Wo);

    gemm_qkv_mma<<<dim3(24, 16), 128, QKV_SMEM>>>(bq, bk, bv);

    attn_mma<<<dim3(32, 8), 256, ATTN_B>>>();

    gemm_o_mma<<<dim3(8, 64), 128, O_SMEM>>>(bo, out);
}

// round 17
// speedup vs baseline: 1.0847x; 1.0847x over previous
#include <cuda_runtime.h>
#include <cuda_fp16.h>
#include <stdint.h>

#define S_LEN 2048
#define DM 512
#define NH 8
#define WIN 64
#define SCALE 0.125f
#define WSZ (512*512)
#define XSZ (2048*512)

// ---------------- scratch (no allocation allowed) ----------------
__device__ __align__(16) __half g_x_hi[XSZ];
__device__ __align__(16) __half g_w_hi[4 * WSZ];
__device__ __align__(16) __half g_q_hi[XSZ];
__device__ __align__(16) __half g_k_hi[XSZ];
__device__ __align__(16) __half g_vt_hi[XSZ];    // [512][2048]
__device__ __align__(16) __half g_a_hi[XSZ];

// ---------------- PTX helpers ----------------
__device__ __forceinline__ uint32_t smem_u32(const void* p) {
    uint32_t a;
    asm("{ .reg .u64 t; cvta.to.shared.u64 t, %1; cvt.u32.u64 %0, t; }"
        : "=r"(a) : "l"(p));
    return a;
}
__device__ __forceinline__ void cp16(uint32_t s, const void* g) {
    asm volatile("cp.async.cg.shared.global [%0], [%1], 16;"
                 :: "r"(s), "l"(g) : "memory");
}
__device__ __forceinline__ void cp_commit() {
    asm volatile("cp.async.commit_group;" ::: "memory");
}
template<int N> __device__ __forceinline__ void cp_wait() {
    asm volatile("cp.async.wait_group %0;" :: "n"(N) : "memory");
}
__device__ __forceinline__ void ldsm_x4(uint32_t& r0, uint32_t& r1,
                                        uint32_t& r2, uint32_t& r3, uint32_t a) {
    asm volatile("ldmatrix.sync.aligned.m8n8.x4.shared.b16 {%0,%1,%2,%3}, [%4];"
                 : "=r"(r0), "=r"(r1), "=r"(r2), "=r"(r3) : "r"(a));
}
__device__ __forceinline__ void mma16816(float c[4], const uint32_t a[4],
                                         const uint32_t b[2]) {
    asm volatile(
        "mma.sync.aligned.m16n8k16.row.col.f32.f16.f16.f32 "
        "{%0,%1,%2,%3}, {%4,%5,%6,%7}, {%8,%9}, {%0,%1,%2,%3};"
        : "+f"(c[0]), "+f"(c[1]), "+f"(c[2]), "+f"(c[3])
        : "r"(a[0]), "r"(a[1]), "r"(a[2]), "r"(a[3]), "r"(b[0]), "r"(b[1]));
}
__device__ __forceinline__ uint32_t pack_h2(float lo, float hi) {
    __half2 h = __halves2half2(__float2half_rn(lo), __float2half_rn(hi));
    return *reinterpret_cast<uint32_t*>(&h);
}

// ---------------- conversion: fp32 -> fp16 ----------------
__global__ __launch_bounds__(256)
void convert_split(const float* __restrict__ x,
                   const float* __restrict__ wq, const float* __restrict__ wk,
                   const float* __restrict__ wv, const float* __restrict__ wo)
{
    const int tn = blockIdx.y;
    const float* src = (tn == 0) ? x : (tn == 1) ? wq : (tn == 2) ? wk
                       : (tn == 3) ? wv : wo;
    const int n = (tn == 0) ? XSZ : WSZ;
    __half* hi = (tn == 0) ? g_x_hi : g_w_hi + (tn - 1) * WSZ;
    int i4 = (blockIdx.x * 256 + threadIdx.x) * 4;
    if (i4 >= n) return;
    float4 v = *reinterpret_cast<const float4*>(&src[i4]);
    reinterpret_cast<__half2*>(hi + i4)[0] =
        __halves2half2(__float2half_rn(v.x), __float2half_rn(v.y));
    reinterpret_cast<__half2*>(hi + i4)[1] =
        __halves2half2(__float2half_rn(v.z), __float2half_rn(v.w));
}

// ---------------- 1-term fp16 GEMM: BMx64 tile, K-chunk=64, 3-stage ring -----
template<int BM>
__device__ __forceinline__ void gemm_body(
    const __half* __restrict__ A, const __half* __restrict__ Bhi,
    const float* __restrict__ bias, int mode,
    __half* __restrict__ oHi,
    float* __restrict__ oF, int rowBase, int colBase)
{
    constexpr int MI   = BM / 32;
    constexpr int OBH  = BM * 144;
    constexpr int GBUF = (BM + 64) * 144;
    constexpr int NAOP = BM * 8;
    constexpr int ITER = (NAOP + 512) / 128;

    extern __shared__ __align__(16) char dynsm[];
    const uint32_t sb = smem_u32(dynsm);
    const int tid = threadIdx.x, lane = tid & 31, wid = tid >> 5;
    const int wm = wid >> 1, wn = wid & 1;
    const int a_row = (lane & 7) + ((lane >> 3) & 1) * 8, a_k = (lane >> 4) * 8;
    const int b_row = (lane & 7) + (lane >> 4) * 8,       b_k = ((lane >> 3) & 1) * 8;

    float acc[MI][4][4] = {};

    auto stage = [&](int buf, int c) {
#pragma unroll
        for (int i = 0; i < ITER; i++) {
            int idx = tid + i * 128;
            const __half* src; int off, rbase, rem;
            if (idx < NAOP) { src = A;   off = 0;   rbase = rowBase; rem = idx; }
            else            { src = Bhi; off = OBH; rbase = colBase; rem = idx - NAOP; }
            int row = rem >> 3, cc = rem & 7;
            cp16(sb + (uint32_t)(buf * GBUF + off + row * 144 + cc * 16),
                 src + ((size_t)(rbase + row) * DM + c * 64 + cc * 8));
        }
        cp_commit();
    };

    stage(0, 0); stage(1, 1);
    for (int c = 0; c < 8; c++) {
        if (c < 7) cp_wait<1>();
        else       cp_wait<0>();
        __syncthreads();
        if (c < 6) stage((c + 2) % 3, c + 2);
        const uint32_t bb = sb + (uint32_t)((c % 3) * GBUF);
#pragma unroll
        for (int k16 = 0; k16 < 4; k16++) {
            uint32_t ah[MI][4], bh[4][2];
#pragma unroll
            for (int mi = 0; mi < MI; mi++) {
                uint32_t o = (uint32_t)((wm * (BM / 2) + mi * 16 + a_row) * 144 +
                                        (k16 * 16 + a_k) * 2);
                ldsm_x4(ah[mi][0], ah[mi][1], ah[mi][2], ah[mi][3], bb + o);
            }
#pragma unroll
            for (int bn = 0; bn < 2; bn++) {
                uint32_t o = (uint32_t)((wn * 32 + bn * 16 + b_row) * 144 +
                                        (k16 * 16 + b_k) * 2);
                uint32_t r0, r1, r2, r3;
                ldsm_x4(r0, r1, r2, r3, bb + OBH + o);
                bh[bn * 2][0] = r0; bh[bn * 2][1] = r1;
                bh[bn * 2 + 1][0] = r2; bh[bn * 2 + 1][1] = r3;
            }
#pragma unroll
            for (int mi = 0; mi < MI; mi++)
#pragma unroll
                for (int ni = 0; ni < 4; ni++)
                    mma16816(acc[mi][ni], ah[mi], bh[ni]);
        }
    }

#pragma unroll
    for (int mi = 0; mi < MI; mi++) {
        int row = rowBase + wm * (BM / 2) + mi * 16 + (lane >> 2);
#pragma unroll
        for (int ni = 0; ni < 4; ni++) {
            int col = colBase + wn * 32 + ni * 8 + (lane & 3) * 2;
            float b0 = bias[col], b1 = bias[col + 1];
            float v00 = acc[mi][ni][0] + b0, v01 = acc[mi][ni][1] + b1;
            float v10 = acc[mi][ni][2] + b0, v11 = acc[mi][ni][3] + b1;
            if (mode == 2) {
                *reinterpret_cast<float2*>(&oF[(size_t)row * DM + col]) =
                    make_float2(v00, v01);
                *reinterpret_cast<float2*>(&oF[(size_t)(row + 8) * DM + col]) =
                    make_float2(v10, v11);
            } else if (mode == 0) {
                *reinterpret_cast<__half2*>(&oHi[(size_t)row * DM + col]) =
                    __halves2half2(__float2half_rn(v00), __float2half_rn(v01));
                *reinterpret_cast<__half2*>(&oHi[(size_t)(row + 8) * DM + col]) =
                    __halves2half2(__float2half_rn(v10), __float2half_rn(v11));
            } else {
                oHi[(size_t)col * S_LEN + row] = __float2half_rn(v00);
                oHi[(size_t)(col + 1) * S_LEN + row] = __float2half_rn(v01);
                oHi[(size_t)col * S_LEN + row + 8] = __float2half_rn(v10);
                oHi[(size_t)(col + 1) * S_LEN + row + 8] = __float2half_rn(v11);
            }
        }
    }
}

#define QKV_SMEM ((64 + 64) * 144 * 3)   // 55296
#define O_SMEM   ((32 + 64) * 144 * 3)   // 41472

__global__ __launch_bounds__(128, 4)
void gemm_qkv_mma(const float* __restrict__ bq, const float* __restrict__ bk,
                  const float* __restrict__ bv)
{
    const int which = blockIdx.x >> 3;
    const int colBase = (blockIdx.x & 7) * 64;
    const int rowBase = blockIdx.y * 64;
    const float* bias = (which == 0) ? bq : (which == 1) ? bk : bv;
    __half* oh; int mode;
    if (which == 0)      { oh = g_q_hi;  mode = 0; }
    else if (which == 1) { oh = g_k_hi;  mode = 0; }
    else                 { oh = g_vt_hi; mode = 1; }
    gemm_body<64>(g_x_hi, g_w_hi + which * WSZ,
                  bias, mode, oh, nullptr, rowBase, colBase);
}

__global__ __launch_bounds__(128, 4)
void gemm_o_mma(const float* __restrict__ bo, float* __restrict__ out)
{
    gemm_body<32>(g_a_hi, g_w_hi + 3 * WSZ,
                  bo, 2, nullptr, out, blockIdx.y * 32, blockIdx.x * 64);
}

// ---------------- register-resident flash attention --------------------------
// 128 threads, 4 warps; warp w owns query rows w*16..w*16+15 (all 192 keys).
// S stays in registers; softmax via 4-lane shuffles; P repacked in-register
// into A-fragments (m16n8 C layout == m16k16 A layout identity); O = P·Vh.
#define AQH 0
#define AKH 9216
#define AVH 36864
#define ATTN_B 62464     // 3 CTAs/SM

__global__ __launch_bounds__(128, 3)
void attn_mma()
{
    extern __shared__ __align__(16) char dynsm[];
    const uint32_t sb = smem_u32(dynsm);
    const int tid = threadIdx.x, lane = tid & 31, wid = tid >> 5;
    const int h = blockIdx.y;
    const int base = blockIdx.x * 64;
    const int j0 = base - WIN;

#pragma unroll
    for (int i = 0; i < 4; i++) {                       // Q [64][64]
        int idx = tid + i * 128;
        int row = idx >> 3, cc = idx & 7;
        cp16(sb + AQH + (uint32_t)(row * 144 + cc * 16),
             g_q_hi + ((size_t)(base + row) * DM + h * 64 + cc * 8));
    }
#pragma unroll
    for (int i = 0; i < 12; i++) {                      // K [192][64]
        int idx = tid + i * 128;
        int row = idx >> 3, cc = idx & 7;
        int j = j0 + row;
        uint32_t off = AKH + (uint32_t)(row * 144 + cc * 16);
        if (j >= 0 && j < S_LEN)
            cp16(sb + off, g_k_hi + ((size_t)j * DM + h * 64 + cc * 8));
        else
            *reinterpret_cast<uint4*>(dynsm + off) = make_uint4(0, 0, 0, 0);
    }
#pragma unroll
    for (int i = 0; i < 12; i++) {                      // V^T [64][192]
        int idx = tid + i * 128;
        int row = idx / 24, cc = idx % 24;
        int j = j0 + cc * 8;
        uint32_t off = AVH + (uint32_t)(row * 400 + cc * 16);
        if (j >= 0 && j + 8 <= S_LEN)
            cp16(sb + off, g_vt_hi + ((size_t)(h * 64 + row) * S_LEN + j));
        else
            *reinterpret_cast<uint4*>(dynsm + off) = make_uint4(0, 0, 0, 0);
    }
    cp_commit();
    cp_wait<0>();
    __syncthreads();

    const int a_row = (lane & 7) + ((lane >> 3) & 1) * 8, a_k = (lane >> 4) * 8;
    const int b_row = (lane & 7) + (lane >> 4) * 8,       b_k = ((lane >> 3) & 1) * 8;

    // ---- S = Qh·Kh^T : warp-private 16x192 accumulator ----
    float sacc[24][4] = {};
#pragma unroll
    for (int k16 = 0; k16 < 4; k16++) {
        uint32_t ah[4];
        uint32_t oA = (uint32_t)((wid * 16 + a_row) * 144 + (k16 * 16 + a_k) * 2);
        ldsm_x4(ah[0], ah[1], ah[2], ah[3], sb + AQH + oA);
#pragma unroll
        for (int t = 0; t < 12; t++) {
            uint32_t oB = (uint32_t)((t * 16 + b_row) * 144 + (k16 * 16 + b_k) * 2);
            uint32_t r0, r1, r2, r3, b0[2], b1[2];
            ldsm_x4(r0, r1, r2, r3, sb + AKH + oB);
            b0[0] = r0; b0[1] = r1; b1[0] = r2; b1[1] = r3;
            mma16816(sacc[t * 2], ah, b0);
            mma16816(sacc[t * 2 + 1], ah, b1);
        }
    }

    // ---- masked softmax in registers (rows m0 and m0+8) ----
    const int m0 = wid * 16 + (lane >> 2);
    const int nlo0 = (m0 > -j0) ? m0 : -j0;
    const int nhi0 = (m0 + 128 < 2047 - j0) ? m0 + 128 : 2047 - j0;
    const int m1 = m0 + 8;
    const int nlo1 = (m1 > -j0) ? m1 : -j0;
    const int nhi1 = (m1 + 128 < 2047 - j0) ? m1 + 128 : 2047 - j0;

    float mx0 = -1e30f, mx1 = -1e30f;
#pragma unroll
    for (int f = 0; f < 24; f++) {
        int n = f * 8 + (lane & 3) * 2;
        float v0 = (n >= nlo0 && n <= nhi0)         ? sacc[f][0] * SCALE : -1e30f;
        float v1 = (n + 1 >= nlo0 && n + 1 <= nhi0) ? sacc[f][1] * SCALE : -1e30f;
        float v2 = (n >= nlo1 && n <= nhi1)         ? sacc[f][2] * SCALE : -1e30f;
        float v3 = (n + 1 >= nlo1 && n + 1 <= nhi1) ? sacc[f][3] * SCALE : -1e30f;
        sacc[f][0] = v0; sacc[f][1] = v1; sacc[f][2] = v2; sacc[f][3] = v3;
        mx0 = fmaxf(mx0, fmaxf(v0, v1));
        mx1 = fmaxf(mx1, fmaxf(v2, v3));
    }
    mx0 = fmaxf(mx0, __shfl_xor_sync(0xffffffffu, mx0, 1));
    mx0 = fmaxf(mx0, __shfl_xor_sync(0xffffffffu, mx0, 2));
    mx1 = fmaxf(mx1, __shfl_xor_sync(0xffffffffu, mx1, 1));
    mx1 = fmaxf(mx1, __shfl_xor_sync(0xffffffffu, mx1, 2));

    float s0 = 0.f, s1 = 0.f;
#pragma unroll
    for (int f = 0; f < 24; f++) {
        float e0 = __expf(sacc[f][0] - mx0);
        float e1 = __expf(sacc[f][1] - mx0);
        float e2 = __expf(sacc[f][2] - mx1);
        float e3 = __expf(sacc[f][3] - mx1);
        sacc[f][0] = e0; sacc[f][1] = e1; sacc[f][2] = e2; sacc[f][3] = e3;
        s0 += e0 + e1; s1 += e2 + e3;
    }
    s0 += __shfl_xor_sync(0xffffffffu, s0, 1);
    s0 += __shfl_xor_sync(0xffffffffu, s0, 2);
    s1 += __shfl_xor_sync(0xffffffffu, s1, 1);
    s1 += __shfl_xor_sync(0xffffffffu, s1, 2);
    const float inv0 = 1.f / s0, inv1 = 1.f / s1;

    // ---- pack P into A-fragments (C-layout == A-layout identity) ----
    uint32_t pf[12][4];
#pragma unroll
    for (int t = 0; t < 12; t++) {
        pf[t][0] = pack_h2(sacc[2*t][0]   * inv0, sacc[2*t][1]   * inv0);
        pf[t][1] = pack_h2(sacc[2*t][2]   * inv1, sacc[2*t][3]   * inv1);
        pf[t][2] = pack_h2(sacc[2*t+1][0] * inv0, sacc[2*t+1][1] * inv0);
        pf[t][3] = pack_h2(sacc[2*t+1][2] * inv1, sacc[2*t+1][3] * inv1);
    }

    // ---- O = P·Vh ----
    float oacc[8][4] = {};
#pragma unroll
    for (int t = 0; t < 12; t++) {
#pragma unroll
        for (int bn = 0; bn < 4; bn++) {
            uint32_t oB = (uint32_t)((bn * 16 + b_row) * 400 + (t * 16 + b_k) * 2);
            uint32_t r0, r1, r2, r3, vh0[2], vh1[2];
            ldsm_x4(r0, r1, r2, r3, sb + AVH + oB);
            vh0[0] = r0; vh0[1] = r1; vh1[0] = r2; vh1[1] = r3;
            mma16816(oacc[bn * 2], pf[t], vh0);
            mma16816(oacc[bn * 2 + 1], pf[t], vh1);
        }
    }
    int row = base + wid * 16 + (lane >> 2);
#pragma unroll
    for (int ni = 0; ni < 8; ni++) {
        int col = h * 64 + ni * 8 + (lane & 3) * 2;
        *reinterpret_cast<__half2*>(&g_a_hi[(size_t)row * DM + col]) =
            __halves2half2(__float2half_rn(oacc[ni][0]), __float2half_rn(oacc[ni][1]));
        *reinterpret_cast<__half2*>(&g_a_hi[(size_t)(row + 8) * DM + col]) =
            __halves2half2(__float2half_rn(oacc[ni][2]), __float2half_rn(oacc[ni][3]));
    }
}

// ---------------- launch ----------------
extern "C" void kernel_launch(void* const* d_in, const int* in_sizes, int n_in,
                              void* d_out, int out_size) {
    const float* x  = (const float*)d_in[0];
    const float* Wq = (const float*)d_in[1];
    const float* bq = (const float*)d_in[2];
    const float* Wk = (const float*)d_in[3];
    const float* bk = (const float*)d_in[4];
    const float* Wv = (const float*)d_in[5];
    const float* bv = (const float*)d_in[6];
    const float* Wo = (const float*)d_in[7];
    const float* bo = (const float*)d_in[8];
    float* out = (float*)d_out;

    cudaFuncSetAttribute(gemm_qkv_mma, cudaFuncAttributeMaxDynamicSharedMemorySize, QKV_SMEM);
    cudaFuncSetAttribute(gemm_o_mma, cudaFuncAttributeMaxDynamicSharedMemorySize, O_SMEM);
    cudaFuncSetAttribute(attn_mma, cudaFuncAttributeMaxDynamicSharedMemorySize, ATTN_B);

    convert_split<<<dim3(XSZ / 1024, 5), 256>>>(x, Wq, Wk, Wv, Wo);

    gemm_qkv_mma<<<dim3(24, 32), 128, QKV_SMEM>>>(bq, bk, bv);

    attn_mma<<<dim3(32, 8), 128, ATTN_B>>>();

    gemm_o_mma<<<dim3(8, 64), 128, O_SMEM>>>(bo, out);
}